// round 2
// baseline (speedup 1.0000x reference)
#include <cuda_runtime.h>
#include <cuda_bf16.h>
#include <cstdint>

// ---------------------------------------------------------------------------
// GCN layer: out = relu( (segment_sum((h@W)*norm [src->dst])) * norm + bias
//                        + h @ res_w^T + res_b )
// Inputs (metadata order):
//   0: h      [100000,256] f32
//   1: norm   [100000,1]   f32
//   2: src    [1600000]    i32
//   3: dst    [1600000]    i32
//   4: weight [256,256]    f32   (in,out)
//   5: bias   [256]        f32
//   6: res_w  [256,256]    f32   (out,in)
//   7: res_b  [256]        f32
// Output: [100000,256] f32
// ---------------------------------------------------------------------------

#define N_NODES 100000
#define N_EDGES 1600000
#define F_IN    256
#define F_OUT   256
#define NN      512           // concatenated GEMM width: [W | res_w^T]

#define BM 128
#define BN 128
#define BK 16

// Scratch (static __device__ arrays: allowed; runtime alloc is not)
__device__ float g_wcat[F_IN * NN];               // 512 KB
__device__ float g_hw  [(size_t)N_NODES * F_OUT]; // 100 MB
__device__ float g_agg [(size_t)N_NODES * F_OUT]; // 100 MB

// ---- packed fp32x2 helpers (sm_100+: fma.rn.f32x2, PTX-only path) ----------
__device__ __forceinline__ unsigned long long ffma2(unsigned long long a,
                                                    unsigned long long b,
                                                    unsigned long long c) {
    unsigned long long d;
    asm("fma.rn.f32x2 %0, %1, %2, %3;" : "=l"(d) : "l"(a), "l"(b), "l"(c));
    return d;
}
__device__ __forceinline__ unsigned long long bcast2(float x) {
    unsigned long long d;
    unsigned int xi = __float_as_uint(x);
    asm("mov.b64 %0, {%1, %1};" : "=l"(d) : "r"(xi));
    return d;
}
__device__ __forceinline__ float2 unpack2(unsigned long long v) {
    unsigned int lo, hi;
    asm("mov.b64 {%0, %1}, %2;" : "=r"(lo), "=r"(hi) : "l"(v));
    float2 r;
    r.x = __uint_as_float(lo);
    r.y = __uint_as_float(hi);
    return r;
}

// ---- vector f32 reduction (sm_90+: red.global.add.v4.f32, PTX-only) --------
__device__ __forceinline__ void red_add_v4(float* p, float4 v) {
    asm volatile("red.global.add.v4.f32 [%0], {%1, %2, %3, %4};"
                 :: "l"(p), "f"(v.x), "f"(v.y), "f"(v.z), "f"(v.w)
                 : "memory");
}

// ---------------------------------------------------------------------------
// K0: build concatenated B matrix g_wcat[k][o]:
//   o <  256 : W[k][o]            (weight is [in,out] row-major)
//   o >= 256 : res_w[o-256][k]    (res_w is [out,in] row-major -> transpose)
// ---------------------------------------------------------------------------
__global__ void prep_wcat_kernel(const float* __restrict__ W,
                                 const float* __restrict__ RW) {
    int k = blockIdx.x;          // 0..255
    int o = threadIdx.x;         // 0..511
    float v;
    if (o < F_OUT) {
        v = W[k * F_OUT + o];
    } else {
        v = RW[(o - F_OUT) * F_IN + k];
    }
    g_wcat[k * NN + o] = v;
}

// ---------------------------------------------------------------------------
// K1: zero the aggregation buffer
// ---------------------------------------------------------------------------
__global__ void zero_agg_kernel() {
    size_t i = (size_t)blockIdx.x * blockDim.x + threadIdx.x;
    float4* p = reinterpret_cast<float4*>(g_agg);
    if (i < (size_t)N_NODES * F_OUT / 4)
        p[i] = make_float4(0.f, 0.f, 0.f, 0.f);
}

// ---------------------------------------------------------------------------
// K2: SGEMM  C[100000,512] = h[100000,256] @ g_wcat[256,512]
//   cols [0,256)  -> g_hw  = acc * norm[row]
//   cols [256,512)-> d_out = acc + bias[c] + res_b[c]   (the "base" term)
// 128x128 block tile, BK=16, 256 threads, 8x8 microtile, packed f32x2 FMA.
// ---------------------------------------------------------------------------
__global__ __launch_bounds__(256, 2)
void sgemm_kernel(const float* __restrict__ A,
                  const float* __restrict__ norm,
                  const float* __restrict__ bias,
                  const float* __restrict__ res_b,
                  float* __restrict__ dout) {
    __shared__ float As[BK][BM + 4];   // +4 pad: keeps 16B alignment, cuts store conflicts
    __shared__ float Bs[BK][BN];

    const int t  = threadIdx.x;
    const int m0 = blockIdx.x * BM;
    const int n0 = blockIdx.y * BN;
    const int tr = t >> 4;            // 0..15
    const int tc = t & 15;            // 0..15

    // A tile loader mapping: 128 rows x 16 cols, float4 per thread, 2 rounds
    const int arow = t >> 2;          // 0..63
    const int acol = (t & 3) * 4;     // 0,4,8,12
    // B tile loader mapping: 16 rows x 128 cols, float4 per thread, 2 rounds
    const int brow = t >> 5;          // 0..7
    const int bcol = (t & 31) * 4;    // 0..124

    unsigned long long acc[8][4];
#pragma unroll
    for (int i = 0; i < 8; i++)
#pragma unroll
        for (int j = 0; j < 4; j++) acc[i][j] = 0ull;

    for (int k0 = 0; k0 < F_IN; k0 += BK) {
        // ---- load A tile (guard row overrun; transpose into As[k][m]) ----
#pragma unroll
        for (int h = 0; h < 2; h++) {
            int r  = arow + h * 64;
            int gm = m0 + r;
            float4 v = make_float4(0.f, 0.f, 0.f, 0.f);
            if (gm < N_NODES)
                v = *reinterpret_cast<const float4*>(&A[(size_t)gm * F_IN + k0 + acol]);
            As[acol + 0][r] = v.x;
            As[acol + 1][r] = v.y;
            As[acol + 2][r] = v.z;
            As[acol + 3][r] = v.w;
        }
        // ---- load B tile ----
#pragma unroll
        for (int h = 0; h < 2; h++) {
            int r = brow + h * 8;
            *reinterpret_cast<float4*>(&Bs[r][bcol]) =
                *reinterpret_cast<const float4*>(&g_wcat[(size_t)(k0 + r) * NN + n0 + bcol]);
        }
        __syncthreads();

        // ---- compute ----
#pragma unroll
        for (int k = 0; k < BK; k++) {
            float4 a0 = *reinterpret_cast<const float4*>(&As[k][tr * 8]);
            float4 a1 = *reinterpret_cast<const float4*>(&As[k][tr * 8 + 4]);
            const unsigned long long* bp =
                reinterpret_cast<const unsigned long long*>(&Bs[k][tc * 8]);
            unsigned long long b2[4] = {bp[0], bp[1], bp[2], bp[3]};
            float am[8] = {a0.x, a0.y, a0.z, a0.w, a1.x, a1.y, a1.z, a1.w};
#pragma unroll
            for (int i = 0; i < 8; i++) {
                unsigned long long a2 = bcast2(am[i]);
#pragma unroll
                for (int j = 0; j < 4; j++)
                    acc[i][j] = ffma2(a2, b2[j], acc[i][j]);
            }
        }
        __syncthreads();
    }

    // ---- epilogue ----
    const bool is_hw = (n0 < F_OUT);
#pragma unroll
    for (int i = 0; i < 8; i++) {
        int gm = m0 + tr * 8 + i;
        if (gm >= N_NODES) continue;
        if (is_hw) {
            float nm = norm[gm];
#pragma unroll
            for (int j = 0; j < 4; j++) {
                float2 v = unpack2(acc[i][j]);
                int gc = n0 + tc * 8 + j * 2;
                g_hw[(size_t)gm * F_OUT + gc]     = v.x * nm;
                g_hw[(size_t)gm * F_OUT + gc + 1] = v.y * nm;
            }
        } else {
#pragma unroll
            for (int j = 0; j < 4; j++) {
                float2 v = unpack2(acc[i][j]);
                int gc = (n0 - F_OUT) + tc * 8 + j * 2;
                dout[(size_t)gm * F_OUT + gc]     = v.x + bias[gc]     + res_b[gc];
                dout[(size_t)gm * F_OUT + gc + 1] = v.y + bias[gc + 1] + res_b[gc + 1];
            }
        }
    }
}

// ---------------------------------------------------------------------------
// K3: edge scatter.  One warp per edge; each lane owns 8 contiguous floats
// (2 float4). Vector RED: red.global.add.v4.f32 -> 1 instruction / 16 bytes.
// g_agg[dst] += g_hw[src]
// ---------------------------------------------------------------------------
__global__ __launch_bounds__(256, 8)
void scatter_kernel(const int* __restrict__ src,
                    const int* __restrict__ dst) {
    size_t gt   = (size_t)blockIdx.x * blockDim.x + threadIdx.x;
    size_t e    = gt >> 5;               // edge index (warp per edge)
    if (e >= N_EDGES) return;
    int lane = (int)(gt & 31);
    int c    = lane << 3;                // 8 floats per lane: 0,8,...,248
    int s = __ldg(&src[e]);              // warp-uniform -> L1 broadcast
    int d = __ldg(&dst[e]);
    const float* sp = &g_hw [(size_t)s * F_OUT + c];
    float*       dp = &g_agg[(size_t)d * F_OUT + c];
    float4 v0 = *reinterpret_cast<const float4*>(sp);
    float4 v1 = *reinterpret_cast<const float4*>(sp + 4);
    red_add_v4(dp,     v0);
    red_add_v4(dp + 4, v1);
}

// ---------------------------------------------------------------------------
// K4: finalize  out = relu(agg * norm + base)   (base already in d_out)
// ---------------------------------------------------------------------------
__global__ void finalize_kernel(const float* __restrict__ norm,
                                float* __restrict__ dout) {
    size_t i = (size_t)blockIdx.x * blockDim.x + threadIdx.x;
    if (i >= (size_t)N_NODES * F_OUT / 4) return;
    int n = (int)(i >> 6);               // 64 float4 per row
    float nm = norm[n];
    float4 a = reinterpret_cast<const float4*>(g_agg)[i];
    float4 b = reinterpret_cast<float4*>(dout)[i];
    float4 r;
    r.x = fmaxf(fmaf(a.x, nm, b.x), 0.f);
    r.y = fmaxf(fmaf(a.y, nm, b.y), 0.f);
    r.z = fmaxf(fmaf(a.z, nm, b.z), 0.f);
    r.w = fmaxf(fmaf(a.w, nm, b.w), 0.f);
    reinterpret_cast<float4*>(dout)[i] = r;
}

// ---------------------------------------------------------------------------
extern "C" void kernel_launch(void* const* d_in, const int* in_sizes, int n_in,
                              void* d_out, int out_size) {
    const float* h      = (const float*)d_in[0];
    const float* norm   = (const float*)d_in[1];
    const int*   src    = (const int*)  d_in[2];
    const int*   dst    = (const int*)  d_in[3];
    const float* weight = (const float*)d_in[4];
    const float* bias   = (const float*)d_in[5];
    const float* res_w  = (const float*)d_in[6];
    const float* res_b  = (const float*)d_in[7];
    float*       out    = (float*)d_out;

    // K0: build [W | res_w^T]
    prep_wcat_kernel<<<F_IN, NN>>>(weight, res_w);

    // K1: zero aggregation buffer (25.6M floats -> 6.4M float4)
    {
        int total = N_NODES * F_OUT / 4;
        zero_agg_kernel<<<(total + 255) / 256, 256>>>();
    }

    // K2: fused GEMM -> g_hw (scaled) and d_out (base = res + res_b + bias)
    {
        dim3 grid((N_NODES + BM - 1) / BM, NN / BN);  // 782 x 4
        sgemm_kernel<<<grid, 256>>>(h, norm, bias, res_b, out);
    }

    // K3: edge scatter-add (warp per edge, vector RED)
    {
        long long threads_total = (long long)N_EDGES * 32;
        int blocks = (int)((threads_total + 255) / 256);
        scatter_kernel<<<blocks, 256>>>(src, dst);
    }

    // K4: finalize
    {
        int total = N_NODES * F_OUT / 4;
        finalize_kernel<<<(total + 255) / 256, 256>>>(norm, out);
    }
}

// round 15
// speedup vs baseline: 1.2538x; 1.2538x over previous
#include <cuda_runtime.h>
#include <cuda_bf16.h>
#include <cstdint>

// ---------------------------------------------------------------------------
// GCN layer: out = relu( (segment_sum((h@W)*norm [src->dst])) * norm + bias
//                        + h @ res_w^T + res_b )
// R15 (= R8 resubmit, broker timeouts): CSR-by-dst aggregation + double-
// buffered SGEMM (2-stage smem pipeline, 1 barrier per K-tile, LDG prefetch).
// ---------------------------------------------------------------------------

#define N_NODES 100000
#define N_EDGES 1600000
#define F_IN    256
#define F_OUT   256
#define NN      512           // concatenated GEMM width: [W | res_w^T]

#define BM 128
#define BN 128
#define BK 16
#define NTILES (F_IN / BK)    // 16

#define NPART ((N_NODES + 255) / 256)   // 391 scan partials

// Scratch (static __device__ arrays: allowed; runtime alloc is not)
__device__ float g_wcat[F_IN * NN];               // 512 KB
__device__ float g_hw  [(size_t)N_NODES * F_OUT]; // 100 MB
__device__ int   g_deg   [N_NODES];
__device__ int   g_base  [N_NODES + 1];
__device__ int   g_cursor[N_NODES];
__device__ int   g_part  [512];
__device__ int   g_esrc  [N_EDGES];               // 6.4 MB

// ---- packed fp32x2 helpers (sm_100+: fma.rn.f32x2, PTX-only path) ----------
__device__ __forceinline__ unsigned long long ffma2(unsigned long long a,
                                                    unsigned long long b,
                                                    unsigned long long c) {
    unsigned long long d;
    asm("fma.rn.f32x2 %0, %1, %2, %3;" : "=l"(d) : "l"(a), "l"(b), "l"(c));
    return d;
}
__device__ __forceinline__ unsigned long long bcast2(float x) {
    unsigned long long d;
    unsigned int xi = __float_as_uint(x);
    asm("mov.b64 %0, {%1, %1};" : "=l"(d) : "r"(xi));
    return d;
}
__device__ __forceinline__ float2 unpack2(unsigned long long v) {
    unsigned int lo, hi;
    asm("mov.b64 {%0, %1}, %2;" : "=r"(lo), "=r"(hi) : "l"(v));
    float2 r;
    r.x = __uint_as_float(lo);
    r.y = __uint_as_float(hi);
    return r;
}

// ---------------------------------------------------------------------------
// K0: build concatenated B matrix [W | res_w^T]
// ---------------------------------------------------------------------------
__global__ void prep_wcat_kernel(const float* __restrict__ W,
                                 const float* __restrict__ RW) {
    int k = blockIdx.x;          // 0..255
    int o = threadIdx.x;         // 0..511
    float v;
    if (o < F_OUT) v = W[k * F_OUT + o];
    else           v = RW[(o - F_OUT) * F_IN + k];
    g_wcat[k * NN + o] = v;
}

// ---------------------------------------------------------------------------
// CSR build: histogram -> exclusive scan (2-level) -> fill
// ---------------------------------------------------------------------------
__global__ void zero_deg_kernel() {
    int i = blockIdx.x * blockDim.x + threadIdx.x;
    if (i < N_NODES) g_deg[i] = 0;
}

__global__ void hist_kernel(const int* __restrict__ dst) {
    int e = blockIdx.x * blockDim.x + threadIdx.x;
    if (e < N_EDGES) atomicAdd(&g_deg[dst[e]], 1);
}

// per-block inclusive scan of deg; writes exclusive (local) to g_base,
// block totals to g_part
__global__ void scan1_kernel() {
    __shared__ int sm[256];
    int t = threadIdx.x;
    int n = blockIdx.x * 256 + t;
    int v = (n < N_NODES) ? g_deg[n] : 0;
    sm[t] = v;
    __syncthreads();
#pragma unroll
    for (int off = 1; off < 256; off <<= 1) {
        int x = (t >= off) ? sm[t - off] : 0;
        __syncthreads();
        sm[t] += x;
        __syncthreads();
    }
    if (n < N_NODES) g_base[n] = sm[t] - v;       // local exclusive
    if (t == 255) g_part[blockIdx.x] = sm[t];      // block total
}

// scan of 391 block partials (single block, 512 threads) -> exclusive
__global__ void scan2_kernel() {
    __shared__ int sm[512];
    int t = threadIdx.x;
    int v = (t < NPART) ? g_part[t] : 0;
    sm[t] = v;
    __syncthreads();
#pragma unroll
    for (int off = 1; off < 512; off <<= 1) {
        int x = (t >= off) ? sm[t - off] : 0;
        __syncthreads();
        sm[t] += x;
        __syncthreads();
    }
    if (t < NPART) g_part[t] = sm[t] - v;          // exclusive block offset
}

// add block offsets, init cursors, set sentinel
__global__ void scan3_kernel() {
    int n = blockIdx.x * blockDim.x + threadIdx.x;
    if (n < N_NODES) {
        int b = g_base[n] + g_part[n >> 8];
        g_base[n]   = b;
        g_cursor[n] = b;
    }
    if (n == 0) g_base[N_NODES] = N_EDGES;
}

__global__ void fill_kernel(const int* __restrict__ src,
                            const int* __restrict__ dst) {
    int e = blockIdx.x * blockDim.x + threadIdx.x;
    if (e < N_EDGES) {
        int pos = atomicAdd(&g_cursor[dst[e]], 1);
        g_esrc[pos] = src[e];
    }
}

// ---------------------------------------------------------------------------
// K2: SGEMM  C[100000,512] = h[100000,256] @ g_wcat[256,512]
//   cols [0,256)  -> g_hw  = acc * norm[row]
//   cols [256,512)-> d_out = acc + bias[c] + res_b[c]   (the "base" term)
// 128x128 tile, BK=16, 256 threads, 8x8 microtile, packed f32x2 FMA.
// 2-stage smem double buffer: prefetch tile k+1 to regs during compute of
// tile k; one __syncthreads per tile. Buffer safety: within an iteration
// computes read buf[cur] while stores hit buf[nxt] (disjoint); the single
// end-of-iter barrier orders iter i's reads of buf[cur] before iter i+1's
// stores to that same buffer.
// ---------------------------------------------------------------------------
__global__ __launch_bounds__(256, 2)
void sgemm_kernel(const float* __restrict__ A,
                  const float* __restrict__ norm,
                  const float* __restrict__ bias,
                  const float* __restrict__ res_b,
                  float* __restrict__ dout) {
    __shared__ float As[2][BK][BM + 4];
    __shared__ float Bs[2][BK][BN];

    const int t  = threadIdx.x;
    const int m0 = blockIdx.x * BM;
    const int n0 = blockIdx.y * BN;
    const int tr = t >> 4;            // 0..15
    const int tc = t & 15;            // 0..15

    // A tile loader mapping: 128 rows x 16 cols, float4 per thread, 2 rounds
    const int arow = t >> 2;          // 0..63
    const int acol = (t & 3) * 4;     // 0,4,8,12
    // B tile loader mapping: 16 rows x 128 cols, float4 per thread, 2 rounds
    const int brow = t >> 5;          // 0..7
    const int bcol = (t & 31) * 4;    // 0..124

    unsigned long long acc[8][4];
#pragma unroll
    for (int i = 0; i < 8; i++)
#pragma unroll
        for (int j = 0; j < 4; j++) acc[i][j] = 0ull;

    // ---- prologue: load tile 0 into stage 0 ----
#pragma unroll
    for (int hh = 0; hh < 2; hh++) {
        int r  = arow + hh * 64;
        int gm = m0 + r;
        float4 v = make_float4(0.f, 0.f, 0.f, 0.f);
        if (gm < N_NODES)
            v = *reinterpret_cast<const float4*>(&A[(size_t)gm * F_IN + acol]);
        As[0][acol + 0][r] = v.x;
        As[0][acol + 1][r] = v.y;
        As[0][acol + 2][r] = v.z;
        As[0][acol + 3][r] = v.w;
    }
#pragma unroll
    for (int hh = 0; hh < 2; hh++) {
        int r = brow + hh * 8;
        *reinterpret_cast<float4*>(&Bs[0][r][bcol]) =
            *reinterpret_cast<const float4*>(&g_wcat[(size_t)r * NN + n0 + bcol]);
    }
    __syncthreads();

    for (int tile = 0; tile < NTILES; tile++) {
        const int cur = tile & 1;
        const int nxt = cur ^ 1;
        const bool has_next = (tile + 1 < NTILES);

        // ---- issue prefetch of next tile into registers ----
        float4 av[2], bv[2];
        if (has_next) {
            int k0 = (tile + 1) * BK;
#pragma unroll
            for (int hh = 0; hh < 2; hh++) {
                int r  = arow + hh * 64;
                int gm = m0 + r;
                av[hh] = make_float4(0.f, 0.f, 0.f, 0.f);
                if (gm < N_NODES)
                    av[hh] = *reinterpret_cast<const float4*>(
                        &A[(size_t)gm * F_IN + k0 + acol]);
            }
#pragma unroll
            for (int hh = 0; hh < 2; hh++) {
                int r = brow + hh * 8;
                bv[hh] = *reinterpret_cast<const float4*>(
                    &g_wcat[(size_t)(k0 + r) * NN + n0 + bcol]);
            }
        }

        // ---- compute on stage cur ----
#pragma unroll
        for (int k = 0; k < BK; k++) {
            float4 a0 = *reinterpret_cast<const float4*>(&As[cur][k][tr * 8]);
            float4 a1 = *reinterpret_cast<const float4*>(&As[cur][k][tr * 8 + 4]);
            const unsigned long long* bp =
                reinterpret_cast<const unsigned long long*>(&Bs[cur][k][tc * 8]);
            unsigned long long b2[4] = {bp[0], bp[1], bp[2], bp[3]};
            float am[8] = {a0.x, a0.y, a0.z, a0.w, a1.x, a1.y, a1.z, a1.w};
#pragma unroll
            for (int i = 0; i < 8; i++) {
                unsigned long long a2 = bcast2(am[i]);
#pragma unroll
                for (int j = 0; j < 4; j++)
                    acc[i][j] = ffma2(a2, b2[j], acc[i][j]);
            }
        }

        // ---- store prefetched tile into stage nxt ----
        if (has_next) {
#pragma unroll
            for (int hh = 0; hh < 2; hh++) {
                int r = arow + hh * 64;
                As[nxt][acol + 0][r] = av[hh].x;
                As[nxt][acol + 1][r] = av[hh].y;
                As[nxt][acol + 2][r] = av[hh].z;
                As[nxt][acol + 3][r] = av[hh].w;
            }
#pragma unroll
            for (int hh = 0; hh < 2; hh++) {
                int r = brow + hh * 8;
                *reinterpret_cast<float4*>(&Bs[nxt][r][bcol]) = bv[hh];
            }
        }
        __syncthreads();
    }

    // ---- epilogue ----
    const bool is_hw = (n0 < F_OUT);
#pragma unroll
    for (int i = 0; i < 8; i++) {
        int gm = m0 + tr * 8 + i;
        if (gm >= N_NODES) continue;
        if (is_hw) {
            float nm = norm[gm];
#pragma unroll
            for (int j = 0; j < 4; j++) {
                float2 v = unpack2(acc[i][j]);
                int gc = n0 + tc * 8 + j * 2;
                g_hw[(size_t)gm * F_OUT + gc]     = v.x * nm;
                g_hw[(size_t)gm * F_OUT + gc + 1] = v.y * nm;
            }
        } else {
#pragma unroll
            for (int j = 0; j < 4; j++) {
                float2 v = unpack2(acc[i][j]);
                int gc = (n0 - F_OUT) + tc * 8 + j * 2;
                dout[(size_t)gm * F_OUT + gc]     = v.x + bias[gc]     + res_b[gc];
                dout[(size_t)gm * F_OUT + gc + 1] = v.y + bias[gc + 1] + res_b[gc + 1];
            }
        }
    }
}

// ---------------------------------------------------------------------------
// K3: CSR aggregation + fused finalize.
// One 256-thread block per dst node; thread t owns feature column t.
//   acc = sum over in-edges of g_hw[src][t]   (coalesced 1KB row reads, no atomics)
//   out = relu(acc * norm[n] + base)          (base already in d_out)
// Unroll x4 exposes MLP=4 on the L2-latency-bound gather.
// __ldcs/__stcs on the 200MB output stream keeps g_hw hot in L2.
// ---------------------------------------------------------------------------
__global__ __launch_bounds__(256, 8)
void agg_kernel(const float* __restrict__ norm,
                float* __restrict__ dout) {
    const int n = blockIdx.x;
    const int t = threadIdx.x;
    const int beg = g_base[n];
    const int end = g_base[n + 1];

    float a0 = 0.f, a1 = 0.f, a2 = 0.f, a3 = 0.f;
    int e = beg;
    for (; e + 4 <= end; e += 4) {
        int s0 = __ldg(&g_esrc[e + 0]);
        int s1 = __ldg(&g_esrc[e + 1]);
        int s2 = __ldg(&g_esrc[e + 2]);
        int s3 = __ldg(&g_esrc[e + 3]);
        float v0 = g_hw[(size_t)s0 * F_OUT + t];
        float v1 = g_hw[(size_t)s1 * F_OUT + t];
        float v2 = g_hw[(size_t)s2 * F_OUT + t];
        float v3 = g_hw[(size_t)s3 * F_OUT + t];
        a0 += v0; a1 += v1; a2 += v2; a3 += v3;
    }
    for (; e < end; e++) {
        int s0 = __ldg(&g_esrc[e]);
        a0 += g_hw[(size_t)s0 * F_OUT + t];
    }
    float acc = (a0 + a1) + (a2 + a3);

    const size_t oi = (size_t)n * F_OUT + t;
    float base = __ldcs(&dout[oi]);
    __stcs(&dout[oi], fmaxf(fmaf(acc, norm[n], base), 0.f));
}

// ---------------------------------------------------------------------------
extern "C" void kernel_launch(void* const* d_in, const int* in_sizes, int n_in,
                              void* d_out, int out_size) {
    const float* h      = (const float*)d_in[0];
    const float* norm   = (const float*)d_in[1];
    const int*   src    = (const int*)  d_in[2];
    const int*   dst    = (const int*)  d_in[3];
    const float* weight = (const float*)d_in[4];
    const float* bias   = (const float*)d_in[5];
    const float* res_w  = (const float*)d_in[6];
    const float* res_b  = (const float*)d_in[7];
    float*       out    = (float*)d_out;

    // weight concat
    prep_wcat_kernel<<<F_IN, NN>>>(weight, res_w);

    // CSR build (by dst)
    zero_deg_kernel<<<NPART, 256>>>();
    hist_kernel<<<(N_EDGES + 255) / 256, 256>>>(dst);
    scan1_kernel<<<NPART, 256>>>();
    scan2_kernel<<<1, 512>>>();
    scan3_kernel<<<NPART, 256>>>();
    fill_kernel<<<(N_EDGES + 255) / 256, 256>>>(src, dst);

    // fused GEMM -> g_hw (scaled) and d_out (base = res + res_b + bias)
    {
        dim3 grid((N_NODES + BM - 1) / BM, NN / BN);  // 782 x 4
        sgemm_kernel<<<grid, 256>>>(h, norm, bias, res_b, out);
    }

    // CSR aggregation + finalize
    agg_kernel<<<N_NODES, 256>>>(norm, out);
}